// round 15
// baseline (speedup 1.0000x reference)
#include <cuda_runtime.h>
#include <cuda_fp16.h>
#include <math_constants.h>
#include <cstdint>

#define BATCH  8
#define SLEN   1024
#define NHEAD  8
#define DMODEL 512
#define DKV    64
#define MROWS  (BATCH * SLEN)   // 8192
#define WSZ    (DMODEL * DMODEL)

// ---------------------------------------------------------------------------
// Scratch (allocation-free: __device__ globals) — plain fp16 everywhere
// ---------------------------------------------------------------------------
__device__ __half g_ah[MROWS * DMODEL];     // A (inputs, later ctx)
__device__ __half g_wh[4 * WSZ];            // wq|wk|wv|wo
__device__ __half g_qh[MROWS * DMODEL];     // [b,h,s,d]
__device__ __half g_kh[MROWS * DMODEL];
__device__ __half g_vh[MROWS * DMODEL];
__device__ uint32_t g_mbits[BATCH * SLEN * (SLEN / 32)];   // 1MB bitmask

// ---------------------------------------------------------------------------
// Baseline-ISA helpers
// ---------------------------------------------------------------------------
__device__ __forceinline__ uint32_t smem_u32(const void* p) {
    uint32_t a;
    asm("{ .reg .u64 t; cvta.to.shared.u64 t, %1; cvt.u32.u64 %0, t; }" : "=r"(a) : "l"(p));
    return a;
}
__device__ __forceinline__ void ldsm_x4(uint32_t& r0, uint32_t& r1, uint32_t& r2,
                                        uint32_t& r3, uint32_t addr) {
    asm volatile("ldmatrix.sync.aligned.m8n8.x4.shared.b16 {%0,%1,%2,%3}, [%4];"
                 : "=r"(r0), "=r"(r1), "=r"(r2), "=r"(r3) : "r"(addr));
}
__device__ __forceinline__ void ldsm_x4t(uint32_t& r0, uint32_t& r1, uint32_t& r2,
                                         uint32_t& r3, uint32_t addr) {
    asm volatile("ldmatrix.sync.aligned.m8n8.x4.trans.shared.b16 {%0,%1,%2,%3}, [%4];"
                 : "=r"(r0), "=r"(r1), "=r"(r2), "=r"(r3) : "r"(addr));
}
__device__ __forceinline__ void mma_f16(float* c, uint32_t a0, uint32_t a1, uint32_t a2,
                                        uint32_t a3, uint32_t b0, uint32_t b1) {
    asm volatile("mma.sync.aligned.m16n8k16.row.col.f32.f16.f16.f32 "
                 "{%0,%1,%2,%3}, {%4,%5,%6,%7}, {%8,%9}, {%0,%1,%2,%3};"
                 : "+f"(c[0]), "+f"(c[1]), "+f"(c[2]), "+f"(c[3])
                 : "r"(a0), "r"(a1), "r"(a2), "r"(a3), "r"(b0), "r"(b1));
}
__device__ __forceinline__ void cpa16(uint32_t s, const void* g) {
    asm volatile("cp.async.cg.shared.global [%0], [%1], 16;" :: "r"(s), "l"(g));
}
#define CPA_COMMIT() asm volatile("cp.async.commit_group;" ::: "memory")
#define CPA_WAIT0()  asm volatile("cp.async.wait_group 0;" ::: "memory")

__device__ __forceinline__ uint32_t pack2f(__half lo, __half hi) {
    return ((uint32_t)__half_as_ushort(hi) << 16) | __half_as_ushort(lo);
}
// raw hardware exp2 (same unit __expf uses, minus its extra multiply)
__device__ __forceinline__ float ex2f(float x) {
    float y;
    asm("ex2.approx.f32 %0, %1;" : "=f"(y) : "f"(x));
    return y;
}
#define SCALE_LOG2E 0.1803368801111204f   // 0.125 * log2(e)

// ---------------------------------------------------------------------------
// Fused setup: inputs cvt | 4x weights cvt | mask bitpack, one launch.
// ---------------------------------------------------------------------------
#define N4_IN (MROWS * DMODEL / 4)
#define NB_IN (N4_IN / 256)                 // 4096
#define N4_W  (WSZ / 4)
#define NB_W  (N4_W / 256)                  // 256
#define NB_MASK 256
#define NWORDS (BATCH * SLEN * (SLEN / 32)) // 262144

__global__ __launch_bounds__(256) void setup_kernel(
    const float* __restrict__ inputs, const float* __restrict__ w0,
    const float* __restrict__ w1, const float* __restrict__ w2,
    const float* __restrict__ w3, const float* __restrict__ mask)
{
    int blk = blockIdx.x;
    if (blk < NB_IN) {
        int i = blk * 256 + threadIdx.x;
        float4 v = ((const float4*)inputs)[i];
        uint32_t h0 = pack2f(__float2half_rn(v.x), __float2half_rn(v.y));
        uint32_t h1 = pack2f(__float2half_rn(v.z), __float2half_rn(v.w));
        ((uint2*)g_ah)[i] = make_uint2(h0, h1);
    } else if (blk < NB_IN + 4 * NB_W) {
        int zb = blk - NB_IN;
        int z = zb / NB_W;
        const float* src = (z == 0) ? w0 : (z == 1) ? w1 : (z == 2) ? w2 : w3;
        int i = (zb % NB_W) * 256 + threadIdx.x;
        float4 v = ((const float4*)src)[i];
        uint32_t h0 = pack2f(__float2half_rn(v.x), __float2half_rn(v.y));
        uint32_t h1 = pack2f(__float2half_rn(v.z), __float2half_rn(v.w));
        ((uint2*)(g_wh + (size_t)z * WSZ))[i] = make_uint2(h0, h1);
    } else {
        int mb = blk - NB_IN - 4 * NB_W;
        int gw = (mb * 256 + threadIdx.x) >> 5;
        int lane = threadIdx.x & 31;
        int nw = (NB_MASK * 256) >> 5;
        for (int w = gw; w < NWORDS; w += nw) {
            float v = mask[(size_t)w * 32 + lane];
            uint32_t bits = __ballot_sync(0xffffffffu, v != 0.f);
            if (lane == 0) g_mbits[w] = bits;
        }
    }
}

// ---------------------------------------------------------------------------
// fp16 GEMM via mma.sync: C = A·W^T + bias (fp32 accumulate).  (frozen)
// ---------------------------------------------------------------------------
#define GKC 32
#define GROWB 80
#define SAR_B (128 * GROWB)            // 10240
#define GSTAGE (2 * SAR_B)             // 20480 per stage
#define GEMM_SMEM (2 * GSTAGE)         // 40960

template <bool QKV>
__global__ __launch_bounds__(256, 2) void mm_kernel(
    const __half* __restrict__ Ah, const __half* __restrict__ Whb,
    const float* __restrict__ b0a, const float* __restrict__ b1a,
    const float* __restrict__ b2a, float* __restrict__ Cout)
{
    extern __shared__ char smem[];
    const uint32_t sb = smem_u32(smem);
    const int tid = threadIdx.x, lane = tid & 31, wid = tid >> 5;
    const int wm = wid & 3, wn = wid >> 2;
    const int bm = blockIdx.y * 128, bn = blockIdx.x * 128;
    const int z = QKV ? blockIdx.z : 0;

    const __half* Bh = Whb + (size_t)z * WSZ;
    const float* bias = QKV ? ((z == 0) ? b0a : (z == 1) ? b1a : b2a) : b0a;

    float acc[2][8][4];
#pragma unroll
    for (int i = 0; i < 2; i++)
#pragma unroll
        for (int j = 0; j < 8; j++)
#pragma unroll
            for (int k = 0; k < 4; k++) acc[i][j][k] = 0.f;

    auto load_chunk = [&](int c, int st) {
        uint32_t dst = sb + st * GSTAGE;
        int k0 = c * GKC;
#pragma unroll
        for (int it = 0; it < 2; it++) {
            int idx = tid + it * 256;
            int r = idx >> 2, cc = idx & 3;
            cpa16(dst + 0 * SAR_B + r * GROWB + cc * 16,
                  Ah + (size_t)(bm + r) * DMODEL + k0 + cc * 8);
            cpa16(dst + 1 * SAR_B + r * GROWB + cc * 16,
                  Bh + (size_t)(bn + r) * DMODEL + k0 + cc * 8);
        }
        CPA_COMMIT();
    };

    load_chunk(0, 0);
    CPA_WAIT0();
    __syncthreads();

    const int m4 = lane >> 3;
    const int half_ = m4 & 1, sub = m4 >> 1;

    for (int c = 0; c < DMODEL / GKC; ++c) {
        int st = c & 1;
        if (c < DMODEL / GKC - 1) load_chunk(c + 1, st ^ 1);
        uint32_t base = sb + st * GSTAGE;

#pragma unroll
        for (int ks = 0; ks < 2; ks++) {
            uint32_t ah[2][4];
#pragma unroll
            for (int mf = 0; mf < 2; mf++) {
                uint32_t row = wm * 32 + mf * 16 + (lane & 15);
                uint32_t col = ks * 32 + ((lane >> 4) << 4);
                ldsm_x4(ah[mf][0], ah[mf][1], ah[mf][2], ah[mf][3],
                        base + 0 * SAR_B + row * GROWB + col);
            }
#pragma unroll
            for (int hg = 0; hg < 2; hg++) {
                uint32_t bh[4][2];
#pragma unroll
                for (int g = 0; g < 2; g++) {
                    uint32_t row = wn * 64 + (hg * 4 + g * 2 + sub) * 8 + (lane & 7);
                    uint32_t ad = base + 1 * SAR_B + row * GROWB + ks * 32 + half_ * 16;
                    ldsm_x4(bh[g * 2][0], bh[g * 2][1], bh[g * 2 + 1][0], bh[g * 2 + 1][1], ad);
                }
#pragma unroll
                for (int mf = 0; mf < 2; mf++)
#pragma unroll
                    for (int nf = 0; nf < 4; nf++)
                        mma_f16(acc[mf][hg * 4 + nf], ah[mf][0], ah[mf][1], ah[mf][2],
                                ah[mf][3], bh[nf][0], bh[nf][1]);
            }
        }
        if (c < DMODEL / GKC - 1) CPA_WAIT0();
        __syncthreads();
    }

    const int q4 = lane & 3, r4 = lane >> 2;
#pragma unroll
    for (int mf = 0; mf < 2; mf++)
#pragma unroll
        for (int nf = 0; nf < 8; nf++) {
            int col = bn + wn * 64 + nf * 8 + q4 * 2;
            float2 bb = *(const float2*)(bias + col);
#pragma unroll
            for (int hh = 0; hh < 2; hh++) {
                int row = bm + wm * 32 + mf * 16 + r4 + hh * 8;
                float v0 = acc[mf][nf][2 * hh + 0] + bb.x;
                float v1 = acc[mf][nf][2 * hh + 1] + bb.y;
                if (!QKV) {
                    *(float2*)(Cout + (size_t)row * DMODEL + col) = make_float2(v0, v1);
                } else {
                    int b = row >> 10, s = row & 1023, hd = col >> 6, d = col & 63;
                    size_t o = ((size_t)((b * NHEAD + hd) * SLEN + s)) * DKV + d;
                    uint32_t hp = pack2f(__float2half_rn(v0), __float2half_rn(v1));
                    __half* dst = (z == 0) ? g_qh : (z == 1) ? g_kh : g_vh;
                    *(uint32_t*)(dst + o) = hp;
                }
            }
        }
}

// ---------------------------------------------------------------------------
// Flash attention, fp16 mma.sync, fixed-max softmax, ex2 fold.
// Block: 128 q-rows x one (b,h). 8 warps / 256 threads, 16 q-rows per warp.
// Halves K/V global re-read traffic vs 64-row blocks.
// ---------------------------------------------------------------------------
#define AROWB 144
#define AT_BYTES (64 * AROWB)            // 9216
#define ABUF (2 * AT_BYTES)              // Kh,Vh = 18432 per stage
#define QSTAGE (128 * AROWB)             // 18432
#define ATTN_SMEM (2 * ABUF + QSTAGE)    // 55296

__global__ __launch_bounds__(256) void attn_kernel()
{
    extern __shared__ char smem[];
    const uint32_t sb = smem_u32(smem);
    const int tid = threadIdx.x, lane = tid & 31, w = tid >> 5;   // w: 0..7
    const int q4 = lane & 3, r4 = lane >> 2;
    const int qt = blockIdx.x, bh = blockIdx.y;
    const int b = bh >> 3, h = bh & 7;

    const __half* Qh = g_qh + (size_t)bh * SLEN * DKV + (size_t)qt * 128 * DKV;
    const __half* Kh = g_kh + (size_t)bh * SLEN * DKV;
    const __half* Vh = g_vh + (size_t)bh * SLEN * DKV;

    // ---- stage 128-row Q, extract fragments ----
    {
        uint32_t qb = sb + 2 * ABUF;
#pragma unroll
        for (int it = 0; it < 4; it++) {
            int idx = tid + it * 256;          // 0..1023
            int r = idx >> 3, cc = idx & 7;
            cpa16(qb + r * AROWB + cc * 16, Qh + r * DKV + cc * 8);
        }
        CPA_COMMIT();
        CPA_WAIT0();
        __syncthreads();
    }
    uint32_t qfh[4][4];
    {
        uint32_t qb = sb + 2 * ABUF;
        uint32_t row = w * 16 + (lane & 15);
#pragma unroll
        for (int ks = 0; ks < 4; ks++) {
            uint32_t col = ks * 32 + ((lane >> 4) << 4);
            ldsm_x4(qfh[ks][0], qfh[ks][1], qfh[ks][2], qfh[ks][3],
                    qb + row * AROWB + col);
        }
    }

    auto load_tile = [&](int kt, int st) {
        uint32_t dst = sb + st * ABUF;
        const __half* srcs[2] = {Kh + (size_t)kt * 64 * DKV, Vh + (size_t)kt * 64 * DKV};
#pragma unroll
        for (int arr = 0; arr < 2; arr++)
#pragma unroll
            for (int it = 0; it < 2; it++) {
                int idx = tid + it * 256;      // 0..511
                int r = idx >> 3, cc = idx & 7;
                cpa16(dst + arr * AT_BYTES + r * AROWB + cc * 16, srcs[arr] + r * DKV + cc * 8);
            }
        CPA_COMMIT();
    };

    load_tile(0, 0);
    CPA_WAIT0();
    __syncthreads();

    float o[8][4];
#pragma unroll
    for (int j = 0; j < 8; j++)
#pragma unroll
        for (int k = 0; k < 4; k++) o[j][k] = 0.f;
    float l0 = 0.f, l1 = 0.f;

    const uint32_t* mrow0 = g_mbits + ((size_t)b * SLEN + qt * 128 + w * 16 + r4) * 32;
    const uint32_t* mrow1 = mrow0 + 8 * 32;

    const int m4 = lane >> 3, half_ = m4 & 1, sub = m4 >> 1;

    for (int kt = 0; kt < 16; ++kt) {
        int st = kt & 1;
        if (kt < 15) load_tile(kt + 1, st ^ 1);
        uint32_t base = sb + st * ABUF;

        // ---- S = Q @ K^T ----
        float s[8][4];
#pragma unroll
        for (int j = 0; j < 8; j++)
#pragma unroll
            for (int k = 0; k < 4; k++) s[j][k] = 0.f;

#pragma unroll
        for (int ks = 0; ks < 4; ks++) {
            uint32_t kh[8][2];
#pragma unroll
            for (int g = 0; g < 4; g++) {
                uint32_t row = (g * 2 + sub) * 8 + (lane & 7);
                uint32_t ad = base + row * AROWB + ks * 32 + half_ * 16;
                ldsm_x4(kh[g * 2][0], kh[g * 2][1], kh[g * 2 + 1][0], kh[g * 2 + 1][1], ad);
            }
#pragma unroll
            for (int nf = 0; nf < 8; nf++)
                mma_f16(s[nf], qfh[ks][0], qfh[ks][1], qfh[ks][2], qfh[ks][3],
                        kh[nf][0], kh[nf][1]);
        }

        // ---- mask + scaled exp2 (fixed max) ----
        uint32_t w0a = mrow0[kt * 2], w0b = mrow0[kt * 2 + 1];
        uint32_t w1a = mrow1[kt * 2], w1b = mrow1[kt * 2 + 1];
        uint32_t pH01[8], pH23[8];
#pragma unroll
        for (int nf = 0; nf < 8; nf++) {
            int c = nf * 8 + q4 * 2;
            uint32_t wr0 = (c < 32) ? w0a : w0b;
            uint32_t wr1 = (c < 32) ? w1a : w1b;
            int sh = c & 31;
            float p0 = ((wr0 >> sh) & 1) ? 0.f : ex2f(s[nf][0] * SCALE_LOG2E);
            float p1 = ((wr0 >> (sh + 1)) & 1) ? 0.f : ex2f(s[nf][1] * SCALE_LOG2E);
            float p2 = ((wr1 >> sh) & 1) ? 0.f : ex2f(s[nf][2] * SCALE_LOG2E);
            float p3 = ((wr1 >> (sh + 1)) & 1) ? 0.f : ex2f(s[nf][3] * SCALE_LOG2E);
            l0 += p0 + p1;
            l1 += p2 + p3;
            pH01[nf] = pack2f(__float2half_rn(p0), __float2half_rn(p1));
            pH23[nf] = pack2f(__float2half_rn(p2), __float2half_rn(p3));
        }

        // ---- O += P @ V ----
#pragma unroll
        for (int ks = 0; ks < 4; ks++) {
            uint32_t a0 = pH01[2 * ks], a1 = pH23[2 * ks];
            uint32_t a2 = pH01[2 * ks + 1], a3 = pH23[2 * ks + 1];
            uint32_t vaddr = (ks * 16 + (lane & 15)) * AROWB + ((lane >> 4) << 4);
            uint32_t vh[16];
#pragma unroll
            for (int nf2 = 0; nf2 < 4; nf2++) {
                ldsm_x4t(vh[nf2 * 4 + 0], vh[nf2 * 4 + 1], vh[nf2 * 4 + 2], vh[nf2 * 4 + 3],
                         base + 1 * AT_BYTES + vaddr + nf2 * 32);
            }
#pragma unroll
            for (int j = 0; j < 8; j++)
                mma_f16(o[j], a0, a1, a2, a3, vh[2 * j], vh[2 * j + 1]);
        }

        if (kt < 15) CPA_WAIT0();
        __syncthreads();
    }

    // ---- one-time row-sum reduction ----
    l0 += __shfl_xor_sync(0xffffffffu, l0, 1);
    l0 += __shfl_xor_sync(0xffffffffu, l0, 2);
    l1 += __shfl_xor_sync(0xffffffffu, l1, 1);
    l1 += __shfl_xor_sync(0xffffffffu, l1, 2);

    // ---- epilogue: ctx = O / l -> fp16 into g_ah ----
    float il0 = (l0 > 0.f) ? (1.f / l0) : 0.f;
    float il1 = (l1 > 0.f) ? (1.f / l1) : 0.f;
    int row0 = qt * 128 + w * 16 + r4;
#pragma unroll
    for (int nf = 0; nf < 8; nf++) {
        int col = h * 64 + nf * 8 + q4 * 2;
        uint32_t hp = pack2f(__float2half_rn(o[nf][0] * il0), __float2half_rn(o[nf][1] * il0));
        *(uint32_t*)(g_ah + (size_t)(b * SLEN + row0) * DMODEL + col) = hp;
        hp = pack2f(__float2half_rn(o[nf][2] * il1), __float2half_rn(o[nf][3] * il1));
        *(uint32_t*)(g_ah + (size_t)(b * SLEN + row0 + 8) * DMODEL + col) = hp;
    }
}

// ---------------------------------------------------------------------------
extern "C" void kernel_launch(void* const* d_in, const int* in_sizes, int n_in,
                              void* d_out, int out_size)
{
    const float* inputs = (const float*)d_in[0];
    const float* mask   = (const float*)d_in[1];
    const float* wq = (const float*)d_in[2];
    const float* bq = (const float*)d_in[3];
    const float* wk = (const float*)d_in[4];
    const float* bk = (const float*)d_in[5];
    const float* wv = (const float*)d_in[6];
    const float* bv = (const float*)d_in[7];
    const float* wo = (const float*)d_in[8];
    const float* bo = (const float*)d_in[9];
    float* out = (float*)d_out;

    __half *ah, *wh;
    cudaGetSymbolAddress((void**)&ah, g_ah);
    cudaGetSymbolAddress((void**)&wh, g_wh);

    setup_kernel<<<NB_IN + 4 * NB_W + NB_MASK, 256>>>(inputs, wq, wk, wv, wo, mask);

    cudaFuncSetAttribute(mm_kernel<true>, cudaFuncAttributeMaxDynamicSharedMemorySize, GEMM_SMEM);
    cudaFuncSetAttribute(mm_kernel<false>, cudaFuncAttributeMaxDynamicSharedMemorySize, GEMM_SMEM);
    cudaFuncSetAttribute(attn_kernel, cudaFuncAttributeMaxDynamicSharedMemorySize, ATTN_SMEM);

    dim3 gqkv(DMODEL / 128, MROWS / 128, 3);   // (4, 64, 3)
    mm_kernel<true><<<gqkv, 256, GEMM_SMEM>>>(ah, wh, bq, bk, bv, nullptr);

    dim3 ga(SLEN / 128, BATCH * NHEAD);        // (8, 64)
    attn_kernel<<<ga, 256, ATTN_SMEM>>>();     // writes ctx fp16 into g_ah

    dim3 go(DMODEL / 128, MROWS / 128);        // (4, 64)
    mm_kernel<false><<<go, 256, GEMM_SMEM>>>(ah, wh + 3 * WSZ,
                                             bo, nullptr, nullptr, out);
}

// round 16
// speedup vs baseline: 1.0655x; 1.0655x over previous
#include <cuda_runtime.h>
#include <cuda_fp16.h>
#include <math_constants.h>
#include <cstdint>

#define BATCH  8
#define SLEN   1024
#define NHEAD  8
#define DMODEL 512
#define DKV    64
#define MROWS  (BATCH * SLEN)   // 8192
#define WSZ    (DMODEL * DMODEL)

// ---------------------------------------------------------------------------
// Scratch (allocation-free: __device__ globals) — plain fp16 everywhere
// ---------------------------------------------------------------------------
__device__ __half g_ah[MROWS * DMODEL];     // A (inputs, later ctx)
__device__ __half g_wh[4 * WSZ];            // wq|wk|wv|wo
__device__ __half g_qh[MROWS * DMODEL];     // [b,h,s,d]
__device__ __half g_kh[MROWS * DMODEL];
__device__ __half g_vh[MROWS * DMODEL];
__device__ uint32_t g_mbits[BATCH * SLEN * (SLEN / 32)];   // 1MB bitmask

// ---------------------------------------------------------------------------
// Baseline-ISA helpers
// ---------------------------------------------------------------------------
__device__ __forceinline__ uint32_t smem_u32(const void* p) {
    uint32_t a;
    asm("{ .reg .u64 t; cvta.to.shared.u64 t, %1; cvt.u32.u64 %0, t; }" : "=r"(a) : "l"(p));
    return a;
}
__device__ __forceinline__ void ldsm_x4(uint32_t& r0, uint32_t& r1, uint32_t& r2,
                                        uint32_t& r3, uint32_t addr) {
    asm volatile("ldmatrix.sync.aligned.m8n8.x4.shared.b16 {%0,%1,%2,%3}, [%4];"
                 : "=r"(r0), "=r"(r1), "=r"(r2), "=r"(r3) : "r"(addr));
}
__device__ __forceinline__ void ldsm_x4t(uint32_t& r0, uint32_t& r1, uint32_t& r2,
                                         uint32_t& r3, uint32_t addr) {
    asm volatile("ldmatrix.sync.aligned.m8n8.x4.trans.shared.b16 {%0,%1,%2,%3}, [%4];"
                 : "=r"(r0), "=r"(r1), "=r"(r2), "=r"(r3) : "r"(addr));
}
__device__ __forceinline__ void mma_f16(float* c, uint32_t a0, uint32_t a1, uint32_t a2,
                                        uint32_t a3, uint32_t b0, uint32_t b1) {
    asm volatile("mma.sync.aligned.m16n8k16.row.col.f32.f16.f16.f32 "
                 "{%0,%1,%2,%3}, {%4,%5,%6,%7}, {%8,%9}, {%0,%1,%2,%3};"
                 : "+f"(c[0]), "+f"(c[1]), "+f"(c[2]), "+f"(c[3])
                 : "r"(a0), "r"(a1), "r"(a2), "r"(a3), "r"(b0), "r"(b1));
}
__device__ __forceinline__ void cpa16(uint32_t s, const void* g) {
    asm volatile("cp.async.cg.shared.global [%0], [%1], 16;" :: "r"(s), "l"(g));
}
#define CPA_COMMIT() asm volatile("cp.async.commit_group;" ::: "memory")
#define CPA_WAIT0()  asm volatile("cp.async.wait_group 0;" ::: "memory")

__device__ __forceinline__ uint32_t pack2f(__half lo, __half hi) {
    return ((uint32_t)__half_as_ushort(hi) << 16) | __half_as_ushort(lo);
}
// raw hardware exp2 (what __expf lowers to, minus its extra multiply)
__device__ __forceinline__ float ex2f(float x) {
    float y;
    asm("ex2.approx.f32 %0, %1;" : "=f"(y) : "f"(x));
    return y;
}
#define SCALE_LOG2E 0.1803368801111204f   // 0.125 * log2(e)

// ---------------------------------------------------------------------------
// Fused setup: inputs cvt | 4x weights cvt | mask bitpack, one launch.
// ---------------------------------------------------------------------------
#define N4_IN (MROWS * DMODEL / 4)
#define NB_IN (N4_IN / 256)                 // 4096
#define N4_W  (WSZ / 4)
#define NB_W  (N4_W / 256)                  // 256
#define NB_MASK 256
#define NWORDS (BATCH * SLEN * (SLEN / 32)) // 262144

__global__ __launch_bounds__(256) void setup_kernel(
    const float* __restrict__ inputs, const float* __restrict__ w0,
    const float* __restrict__ w1, const float* __restrict__ w2,
    const float* __restrict__ w3, const float* __restrict__ mask)
{
    int blk = blockIdx.x;
    if (blk < NB_IN) {
        int i = blk * 256 + threadIdx.x;
        float4 v = ((const float4*)inputs)[i];
        uint32_t h0 = pack2f(__float2half_rn(v.x), __float2half_rn(v.y));
        uint32_t h1 = pack2f(__float2half_rn(v.z), __float2half_rn(v.w));
        ((uint2*)g_ah)[i] = make_uint2(h0, h1);
    } else if (blk < NB_IN + 4 * NB_W) {
        int zb = blk - NB_IN;
        int z = zb / NB_W;
        const float* src = (z == 0) ? w0 : (z == 1) ? w1 : (z == 2) ? w2 : w3;
        int i = (zb % NB_W) * 256 + threadIdx.x;
        float4 v = ((const float4*)src)[i];
        uint32_t h0 = pack2f(__float2half_rn(v.x), __float2half_rn(v.y));
        uint32_t h1 = pack2f(__float2half_rn(v.z), __float2half_rn(v.w));
        ((uint2*)(g_wh + (size_t)z * WSZ))[i] = make_uint2(h0, h1);
    } else {
        int mb = blk - NB_IN - 4 * NB_W;
        int gw = (mb * 256 + threadIdx.x) >> 5;
        int lane = threadIdx.x & 31;
        int nw = (NB_MASK * 256) >> 5;
        for (int w = gw; w < NWORDS; w += nw) {
            float v = mask[(size_t)w * 32 + lane];
            uint32_t bits = __ballot_sync(0xffffffffu, v != 0.f);
            if (lane == 0) g_mbits[w] = bits;
        }
    }
}

// ---------------------------------------------------------------------------
// fp16 GEMM via mma.sync: C = A·W^T + bias (fp32 accumulate).
// block 128x128, 256 threads / 8 warps (warp tile 32x64), KC=64 (8 iterations,
// half the barriers of KC=32), double buffer, 2 blocks/SM.
// ---------------------------------------------------------------------------
#define GKC 64
#define GROWB 144                      // 64 halves = 128B + 16B pad
#define SAR_B (128 * GROWB)            // 18432
#define GSTAGE (2 * SAR_B)             // A, W = 36864 per stage
#define GEMM_SMEM (2 * GSTAGE)         // 73728 -> 2 blocks/SM (147KB < 228KB)

template <bool QKV>
__global__ __launch_bounds__(256, 2) void mm_kernel(
    const __half* __restrict__ Ah, const __half* __restrict__ Whb,
    const float* __restrict__ b0a, const float* __restrict__ b1a,
    const float* __restrict__ b2a, float* __restrict__ Cout)
{
    extern __shared__ char smem[];
    const uint32_t sb = smem_u32(smem);
    const int tid = threadIdx.x, lane = tid & 31, wid = tid >> 5;
    const int wm = wid & 3, wn = wid >> 2;
    const int bm = blockIdx.y * 128, bn = blockIdx.x * 128;
    const int z = QKV ? blockIdx.z : 0;

    const __half* Bh = Whb + (size_t)z * WSZ;
    const float* bias = QKV ? ((z == 0) ? b0a : (z == 1) ? b1a : b2a) : b0a;

    float acc[2][8][4];
#pragma unroll
    for (int i = 0; i < 2; i++)
#pragma unroll
        for (int j = 0; j < 8; j++)
#pragma unroll
            for (int k = 0; k < 4; k++) acc[i][j][k] = 0.f;

    auto load_chunk = [&](int c, int st) {
        uint32_t dst = sb + st * GSTAGE;
        int k0 = c * GKC;
#pragma unroll
        for (int it = 0; it < 4; it++) {
            int idx = tid + it * 256;          // 0..1023
            int r = idx >> 3, cc = idx & 7;    // 128 rows x 8 chunks of 16B
            cpa16(dst + 0 * SAR_B + r * GROWB + cc * 16,
                  Ah + (size_t)(bm + r) * DMODEL + k0 + cc * 8);
            cpa16(dst + 1 * SAR_B + r * GROWB + cc * 16,
                  Bh + (size_t)(bn + r) * DMODEL + k0 + cc * 8);
        }
        CPA_COMMIT();
    };

    load_chunk(0, 0);
    CPA_WAIT0();
    __syncthreads();

    const int m4 = lane >> 3;
    const int half_ = m4 & 1, sub = m4 >> 1;

    for (int c = 0; c < DMODEL / GKC; ++c) {      // 8 iterations
        int st = c & 1;
        if (c < DMODEL / GKC - 1) load_chunk(c + 1, st ^ 1);
        uint32_t base = sb + st * GSTAGE;

#pragma unroll
        for (int ks = 0; ks < 4; ks++) {          // 4 k-steps of 16
            uint32_t ah[2][4];
#pragma unroll
            for (int mf = 0; mf < 2; mf++) {
                uint32_t row = wm * 32 + mf * 16 + (lane & 15);
                uint32_t col = ks * 32 + ((lane >> 4) << 4);
                ldsm_x4(ah[mf][0], ah[mf][1], ah[mf][2], ah[mf][3],
                        base + 0 * SAR_B + row * GROWB + col);
            }
#pragma unroll
            for (int hg = 0; hg < 2; hg++) {
                uint32_t bh[4][2];
#pragma unroll
                for (int g = 0; g < 2; g++) {
                    uint32_t row = wn * 64 + (hg * 4 + g * 2 + sub) * 8 + (lane & 7);
                    uint32_t ad = base + 1 * SAR_B + row * GROWB + ks * 32 + half_ * 16;
                    ldsm_x4(bh[g * 2][0], bh[g * 2][1], bh[g * 2 + 1][0], bh[g * 2 + 1][1], ad);
                }
#pragma unroll
                for (int mf = 0; mf < 2; mf++)
#pragma unroll
                    for (int nf = 0; nf < 4; nf++)
                        mma_f16(acc[mf][hg * 4 + nf], ah[mf][0], ah[mf][1], ah[mf][2],
                                ah[mf][3], bh[nf][0], bh[nf][1]);
            }
        }
        if (c < DMODEL / GKC - 1) CPA_WAIT0();
        __syncthreads();
    }

    const int q4 = lane & 3, r4 = lane >> 2;
#pragma unroll
    for (int mf = 0; mf < 2; mf++)
#pragma unroll
        for (int nf = 0; nf < 8; nf++) {
            int col = bn + wn * 64 + nf * 8 + q4 * 2;
            float2 bb = *(const float2*)(bias + col);
#pragma unroll
            for (int hh = 0; hh < 2; hh++) {
                int row = bm + wm * 32 + mf * 16 + r4 + hh * 8;
                float v0 = acc[mf][nf][2 * hh + 0] + bb.x;
                float v1 = acc[mf][nf][2 * hh + 1] + bb.y;
                if (!QKV) {
                    *(float2*)(Cout + (size_t)row * DMODEL + col) = make_float2(v0, v1);
                } else {
                    int b = row >> 10, s = row & 1023, hd = col >> 6, d = col & 63;
                    size_t o = ((size_t)((b * NHEAD + hd) * SLEN + s)) * DKV + d;
                    uint32_t hp = pack2f(__float2half_rn(v0), __float2half_rn(v1));
                    __half* dst = (z == 0) ? g_qh : (z == 1) ? g_kh : g_vh;
                    *(uint32_t*)(dst + o) = hp;
                }
            }
        }
}

// ---------------------------------------------------------------------------
// Flash attention, fp16 mma.sync, fixed-max softmax + ex2 fold.
// Block: 64 q-rows x one (b,h). 4 warps / 128 threads (R14 shape — frozen).
// ---------------------------------------------------------------------------
#define AROWB 144
#define AT_BYTES (64 * AROWB)            // 9216
#define ABUF (2 * AT_BYTES)              // Kh,Vh = 18432 per stage
#define ATTN_SMEM (2 * ABUF + AT_BYTES)  // + Q staging = 46080

__global__ __launch_bounds__(128) void attn_kernel()
{
    extern __shared__ char smem[];
    const uint32_t sb = smem_u32(smem);
    const int tid = threadIdx.x, lane = tid & 31, w = tid >> 5;
    const int q4 = lane & 3, r4 = lane >> 2;
    const int qt = blockIdx.x, bh = blockIdx.y;
    const int b = bh >> 3, h = bh & 7;

    const __half* Qh = g_qh + (size_t)bh * SLEN * DKV + (size_t)qt * 64 * DKV;
    const __half* Kh = g_kh + (size_t)bh * SLEN * DKV;
    const __half* Vh = g_vh + (size_t)bh * SLEN * DKV;

    // ---- stage Q, extract fragments ----
    {
        uint32_t qb = sb + 2 * ABUF;
#pragma unroll
        for (int it = 0; it < 4; it++) {
            int idx = tid + it * 128;
            int r = idx >> 3, cc = idx & 7;
            cpa16(qb + r * AROWB + cc * 16, Qh + r * DKV + cc * 8);
        }
        CPA_COMMIT();
        CPA_WAIT0();
        __syncthreads();
    }
    uint32_t qfh[4][4];
    {
        uint32_t qb = sb + 2 * ABUF;
        uint32_t row = w * 16 + (lane & 15);
#pragma unroll
        for (int ks = 0; ks < 4; ks++) {
            uint32_t col = ks * 32 + ((lane >> 4) << 4);
            ldsm_x4(qfh[ks][0], qfh[ks][1], qfh[ks][2], qfh[ks][3],
                    qb + row * AROWB + col);
        }
    }

    auto load_tile = [&](int kt, int st) {
        uint32_t dst = sb + st * ABUF;
        const __half* srcs[2] = {Kh + (size_t)kt * 64 * DKV, Vh + (size_t)kt * 64 * DKV};
#pragma unroll
        for (int arr = 0; arr < 2; arr++)
#pragma unroll
            for (int it = 0; it < 4; it++) {
                int idx = tid + it * 128;
                int r = idx >> 3, cc = idx & 7;
                cpa16(dst + arr * AT_BYTES + r * AROWB + cc * 16, srcs[arr] + r * DKV + cc * 8);
            }
        CPA_COMMIT();
    };

    load_tile(0, 0);
    CPA_WAIT0();
    __syncthreads();

    float o[8][4];
#pragma unroll
    for (int j = 0; j < 8; j++)
#pragma unroll
        for (int k = 0; k < 4; k++) o[j][k] = 0.f;
    float l0 = 0.f, l1 = 0.f;

    const uint32_t* mrow0 = g_mbits + ((size_t)b * SLEN + qt * 64 + w * 16 + r4) * 32;
    const uint32_t* mrow1 = mrow0 + 8 * 32;

    const int m4 = lane >> 3, half_ = m4 & 1, sub = m4 >> 1;

    for (int kt = 0; kt < 16; ++kt) {
        int st = kt & 1;
        if (kt < 15) load_tile(kt + 1, st ^ 1);
        uint32_t base = sb + st * ABUF;

        // ---- S = Q @ K^T ----
        float s[8][4];
#pragma unroll
        for (int j = 0; j < 8; j++)
#pragma unroll
            for (int k = 0; k < 4; k++) s[j][k] = 0.f;

#pragma unroll
        for (int ks = 0; ks < 4; ks++) {
            uint32_t kh[8][2];
#pragma unroll
            for (int g = 0; g < 4; g++) {
                uint32_t row = (g * 2 + sub) * 8 + (lane & 7);
                uint32_t ad = base + row * AROWB + ks * 32 + half_ * 16;
                ldsm_x4(kh[g * 2][0], kh[g * 2][1], kh[g * 2 + 1][0], kh[g * 2 + 1][1], ad);
            }
#pragma unroll
            for (int nf = 0; nf < 8; nf++)
                mma_f16(s[nf], qfh[ks][0], qfh[ks][1], qfh[ks][2], qfh[ks][3],
                        kh[nf][0], kh[nf][1]);
        }

        // ---- mask + scaled exp2 (fixed max) ----
        uint32_t w0a = mrow0[kt * 2], w0b = mrow0[kt * 2 + 1];
        uint32_t w1a = mrow1[kt * 2], w1b = mrow1[kt * 2 + 1];
        uint32_t pH01[8], pH23[8];
#pragma unroll
        for (int nf = 0; nf < 8; nf++) {
            int c = nf * 8 + q4 * 2;
            uint32_t wr0 = (c < 32) ? w0a : w0b;
            uint32_t wr1 = (c < 32) ? w1a : w1b;
            int sh = c & 31;
            float p0 = ((wr0 >> sh) & 1) ? 0.f : ex2f(s[nf][0] * SCALE_LOG2E);
            float p1 = ((wr0 >> (sh + 1)) & 1) ? 0.f : ex2f(s[nf][1] * SCALE_LOG2E);
            float p2 = ((wr1 >> sh) & 1) ? 0.f : ex2f(s[nf][2] * SCALE_LOG2E);
            float p3 = ((wr1 >> (sh + 1)) & 1) ? 0.f : ex2f(s[nf][3] * SCALE_LOG2E);
            l0 += p0 + p1;
            l1 += p2 + p3;
            pH01[nf] = pack2f(__float2half_rn(p0), __float2half_rn(p1));
            pH23[nf] = pack2f(__float2half_rn(p2), __float2half_rn(p3));
        }

        // ---- O += P @ V ----
#pragma unroll
        for (int ks = 0; ks < 4; ks++) {
            uint32_t a0 = pH01[2 * ks], a1 = pH23[2 * ks];
            uint32_t a2 = pH01[2 * ks + 1], a3 = pH23[2 * ks + 1];
            uint32_t vaddr = (ks * 16 + (lane & 15)) * AROWB + ((lane >> 4) << 4);
            uint32_t vh[16];
#pragma unroll
            for (int nf2 = 0; nf2 < 4; nf2++) {
                ldsm_x4t(vh[nf2 * 4 + 0], vh[nf2 * 4 + 1], vh[nf2 * 4 + 2], vh[nf2 * 4 + 3],
                         base + 1 * AT_BYTES + vaddr + nf2 * 32);
            }
#pragma unroll
            for (int j = 0; j < 8; j++)
                mma_f16(o[j], a0, a1, a2, a3, vh[2 * j], vh[2 * j + 1]);
        }

        if (kt < 15) CPA_WAIT0();
        __syncthreads();
    }

    // ---- one-time row-sum reduction ----
    l0 += __shfl_xor_sync(0xffffffffu, l0, 1);
    l0 += __shfl_xor_sync(0xffffffffu, l0, 2);
    l1 += __shfl_xor_sync(0xffffffffu, l1, 1);
    l1 += __shfl_xor_sync(0xffffffffu, l1, 2);

    // ---- epilogue: ctx = O / l -> fp16 into g_ah ----
    float il0 = (l0 > 0.f) ? (1.f / l0) : 0.f;
    float il1 = (l1 > 0.f) ? (1.f / l1) : 0.f;
    int row0 = qt * 64 + w * 16 + r4;
#pragma unroll
    for (int nf = 0; nf < 8; nf++) {
        int col = h * 64 + nf * 8 + q4 * 2;
        uint32_t hp = pack2f(__float2half_rn(o[nf][0] * il0), __float2half_rn(o[nf][1] * il0));
        *(uint32_t*)(g_ah + (size_t)(b * SLEN + row0) * DMODEL + col) = hp;
        hp = pack2f(__float2half_rn(o[nf][2] * il1), __float2half_rn(o[nf][3] * il1));
        *(uint32_t*)(g_ah + (size_t)(b * SLEN + row0 + 8) * DMODEL + col) = hp;
    }
}

// ---------------------------------------------------------------------------
extern "C" void kernel_launch(void* const* d_in, const int* in_sizes, int n_in,
                              void* d_out, int out_size)
{
    const float* inputs = (const float*)d_in[0];
    const float* mask   = (const float*)d_in[1];
    const float* wq = (const float*)d_in[2];
    const float* bq = (const float*)d_in[3];
    const float* wk = (const float*)d_in[4];
    const float* bk = (const float*)d_in[5];
    const float* wv = (const float*)d_in[6];
    const float* bv = (const float*)d_in[7];
    const float* wo = (const float*)d_in[8];
    const float* bo = (const float*)d_in[9];
    float* out = (float*)d_out;

    __half *ah, *wh;
    cudaGetSymbolAddress((void**)&ah, g_ah);
    cudaGetSymbolAddress((void**)&wh, g_wh);

    setup_kernel<<<NB_IN + 4 * NB_W + NB_MASK, 256>>>(inputs, wq, wk, wv, wo, mask);

    cudaFuncSetAttribute(mm_kernel<true>, cudaFuncAttributeMaxDynamicSharedMemorySize, GEMM_SMEM);
    cudaFuncSetAttribute(mm_kernel<false>, cudaFuncAttributeMaxDynamicSharedMemorySize, GEMM_SMEM);
    cudaFuncSetAttribute(attn_kernel, cudaFuncAttributeMaxDynamicSharedMemorySize, ATTN_SMEM);

    dim3 gqkv(DMODEL / 128, MROWS / 128, 3);   // (4, 64, 3)
    mm_kernel<true><<<gqkv, 256, GEMM_SMEM>>>(ah, wh, bq, bk, bv, nullptr);

    dim3 ga(SLEN / 64, BATCH * NHEAD);         // (16, 64)
    attn_kernel<<<ga, 128, ATTN_SMEM>>>();     // writes ctx fp16 into g_ah

    dim3 go(DMODEL / 128, MROWS / 128);        // (4, 64)
    mm_kernel<false><<<go, 256, GEMM_SMEM>>>(ah, wh + 3 * WSZ,
                                             bo, nullptr, nullptr, out);
}

// round 17
// speedup vs baseline: 1.0767x; 1.0106x over previous
#include <cuda_runtime.h>
#include <cuda_fp16.h>
#include <math_constants.h>
#include <cstdint>

#define BATCH  8
#define SLEN   1024
#define NHEAD  8
#define DMODEL 512
#define DKV    64
#define MROWS  (BATCH * SLEN)   // 8192
#define WSZ    (DMODEL * DMODEL)

// ---------------------------------------------------------------------------
// Scratch (allocation-free: __device__ globals) — plain fp16 everywhere
// ---------------------------------------------------------------------------
__device__ __half g_ah[MROWS * DMODEL];     // A (inputs, later ctx)
__device__ __half g_wh[4 * WSZ];            // wq|wk|wv|wo
__device__ __half g_qh[MROWS * DMODEL];     // [b,h,s,d] (pre-scaled by 0.125*log2e)
__device__ __half g_kh[MROWS * DMODEL];
__device__ __half g_vh[MROWS * DMODEL];
__device__ uint32_t g_mbits[BATCH * SLEN * (SLEN / 32)];   // 1MB bitmask

// ---------------------------------------------------------------------------
// Baseline-ISA helpers
// ---------------------------------------------------------------------------
__device__ __forceinline__ uint32_t smem_u32(const void* p) {
    uint32_t a;
    asm("{ .reg .u64 t; cvta.to.shared.u64 t, %1; cvt.u32.u64 %0, t; }" : "=r"(a) : "l"(p));
    return a;
}
__device__ __forceinline__ void ldsm_x4(uint32_t& r0, uint32_t& r1, uint32_t& r2,
                                        uint32_t& r3, uint32_t addr) {
    asm volatile("ldmatrix.sync.aligned.m8n8.x4.shared.b16 {%0,%1,%2,%3}, [%4];"
                 : "=r"(r0), "=r"(r1), "=r"(r2), "=r"(r3) : "r"(addr));
}
__device__ __forceinline__ void ldsm_x4t(uint32_t& r0, uint32_t& r1, uint32_t& r2,
                                         uint32_t& r3, uint32_t addr) {
    asm volatile("ldmatrix.sync.aligned.m8n8.x4.trans.shared.b16 {%0,%1,%2,%3}, [%4];"
                 : "=r"(r0), "=r"(r1), "=r"(r2), "=r"(r3) : "r"(addr));
}
__device__ __forceinline__ void mma_f16(float* c, uint32_t a0, uint32_t a1, uint32_t a2,
                                        uint32_t a3, uint32_t b0, uint32_t b1) {
    asm volatile("mma.sync.aligned.m16n8k16.row.col.f32.f16.f16.f32 "
                 "{%0,%1,%2,%3}, {%4,%5,%6,%7}, {%8,%9}, {%0,%1,%2,%3};"
                 : "+f"(c[0]), "+f"(c[1]), "+f"(c[2]), "+f"(c[3])
                 : "r"(a0), "r"(a1), "r"(a2), "r"(a3), "r"(b0), "r"(b1));
}
__device__ __forceinline__ void cpa16(uint32_t s, const void* g) {
    asm volatile("cp.async.cg.shared.global [%0], [%1], 16;" :: "r"(s), "l"(g));
}
#define CPA_COMMIT() asm volatile("cp.async.commit_group;" ::: "memory")
#define CPA_WAIT0()  asm volatile("cp.async.wait_group 0;" ::: "memory")
#define CPA_WAIT1()  asm volatile("cp.async.wait_group 1;" ::: "memory")
#define CPA_WAIT2()  asm volatile("cp.async.wait_group 2;" ::: "memory")

__device__ __forceinline__ uint32_t pack2f(__half lo, __half hi) {
    return ((uint32_t)__half_as_ushort(hi) << 16) | __half_as_ushort(lo);
}
// raw hardware exp2
__device__ __forceinline__ float ex2f(float x) {
    float y;
    asm("ex2.approx.f32 %0, %1;" : "=f"(y) : "f"(x));
    return y;
}
#define SCALE_LOG2E 0.1803368801111204f   // 0.125 * log2(e)

// ---------------------------------------------------------------------------
// Fused setup: inputs cvt | 4x weights cvt | mask bitpack, one launch.
// ---------------------------------------------------------------------------
#define N4_IN (MROWS * DMODEL / 4)
#define NB_IN (N4_IN / 256)                 // 4096
#define N4_W  (WSZ / 4)
#define NB_W  (N4_W / 256)                  // 256
#define NB_MASK 256
#define NWORDS (BATCH * SLEN * (SLEN / 32)) // 262144

__global__ __launch_bounds__(256) void setup_kernel(
    const float* __restrict__ inputs, const float* __restrict__ w0,
    const float* __restrict__ w1, const float* __restrict__ w2,
    const float* __restrict__ w3, const float* __restrict__ mask)
{
    int blk = blockIdx.x;
    if (blk < NB_IN) {
        int i = blk * 256 + threadIdx.x;
        float4 v = ((const float4*)inputs)[i];
        uint32_t h0 = pack2f(__float2half_rn(v.x), __float2half_rn(v.y));
        uint32_t h1 = pack2f(__float2half_rn(v.z), __float2half_rn(v.w));
        ((uint2*)g_ah)[i] = make_uint2(h0, h1);
    } else if (blk < NB_IN + 4 * NB_W) {
        int zb = blk - NB_IN;
        int z = zb / NB_W;
        const float* src = (z == 0) ? w0 : (z == 1) ? w1 : (z == 2) ? w2 : w3;
        int i = (zb % NB_W) * 256 + threadIdx.x;
        float4 v = ((const float4*)src)[i];
        uint32_t h0 = pack2f(__float2half_rn(v.x), __float2half_rn(v.y));
        uint32_t h1 = pack2f(__float2half_rn(v.z), __float2half_rn(v.w));
        ((uint2*)(g_wh + (size_t)z * WSZ))[i] = make_uint2(h0, h1);
    } else {
        int mb = blk - NB_IN - 4 * NB_W;
        int gw = (mb * 256 + threadIdx.x) >> 5;
        int lane = threadIdx.x & 31;
        int nw = (NB_MASK * 256) >> 5;
        for (int w = gw; w < NWORDS; w += nw) {
            float v = mask[(size_t)w * 32 + lane];
            uint32_t bits = __ballot_sync(0xffffffffu, v != 0.f);
            if (lane == 0) g_mbits[w] = bits;
        }
    }
}

// ---------------------------------------------------------------------------
// fp16 GEMM via mma.sync: C = A·W^T + bias (fp32 accumulate).
// block 128x128, 256 threads / 8 warps (warp tile 32x64), KC=64, 2 blocks/SM.
// z==0 (Q) output is pre-scaled by 0.125*log2e (softmax fold).
// ---------------------------------------------------------------------------
#define GKC 64
#define GROWB 144
#define SAR_B (128 * GROWB)            // 18432
#define GSTAGE (2 * SAR_B)             // 36864 per stage
#define GEMM_SMEM (2 * GSTAGE)         // 73728

template <bool QKV>
__global__ __launch_bounds__(256, 2) void mm_kernel(
    const __half* __restrict__ Ah, const __half* __restrict__ Whb,
    const float* __restrict__ b0a, const float* __restrict__ b1a,
    const float* __restrict__ b2a, float* __restrict__ Cout)
{
    extern __shared__ char smem[];
    const uint32_t sb = smem_u32(smem);
    const int tid = threadIdx.x, lane = tid & 31, wid = tid >> 5;
    const int wm = wid & 3, wn = wid >> 2;
    const int bm = blockIdx.y * 128, bn = blockIdx.x * 128;
    const int z = QKV ? blockIdx.z : 0;

    const __half* Bh = Whb + (size_t)z * WSZ;
    const float* bias = QKV ? ((z == 0) ? b0a : (z == 1) ? b1a : b2a) : b0a;

    float acc[2][8][4];
#pragma unroll
    for (int i = 0; i < 2; i++)
#pragma unroll
        for (int j = 0; j < 8; j++)
#pragma unroll
            for (int k = 0; k < 4; k++) acc[i][j][k] = 0.f;

    auto load_chunk = [&](int c, int st) {
        uint32_t dst = sb + st * GSTAGE;
        int k0 = c * GKC;
#pragma unroll
        for (int it = 0; it < 4; it++) {
            int idx = tid + it * 256;
            int r = idx >> 3, cc = idx & 7;
            cpa16(dst + 0 * SAR_B + r * GROWB + cc * 16,
                  Ah + (size_t)(bm + r) * DMODEL + k0 + cc * 8);
            cpa16(dst + 1 * SAR_B + r * GROWB + cc * 16,
                  Bh + (size_t)(bn + r) * DMODEL + k0 + cc * 8);
        }
        CPA_COMMIT();
    };

    load_chunk(0, 0);
    CPA_WAIT0();
    __syncthreads();

    const int m4 = lane >> 3;
    const int half_ = m4 & 1, sub = m4 >> 1;

    for (int c = 0; c < DMODEL / GKC; ++c) {
        int st = c & 1;
        if (c < DMODEL / GKC - 1) load_chunk(c + 1, st ^ 1);
        uint32_t base = sb + st * GSTAGE;

#pragma unroll
        for (int ks = 0; ks < 4; ks++) {
            uint32_t ah[2][4];
#pragma unroll
            for (int mf = 0; mf < 2; mf++) {
                uint32_t row = wm * 32 + mf * 16 + (lane & 15);
                uint32_t col = ks * 32 + ((lane >> 4) << 4);
                ldsm_x4(ah[mf][0], ah[mf][1], ah[mf][2], ah[mf][3],
                        base + 0 * SAR_B + row * GROWB + col);
            }
#pragma unroll
            for (int hg = 0; hg < 2; hg++) {
                uint32_t bh[4][2];
#pragma unroll
                for (int g = 0; g < 2; g++) {
                    uint32_t row = wn * 64 + (hg * 4 + g * 2 + sub) * 8 + (lane & 7);
                    uint32_t ad = base + 1 * SAR_B + row * GROWB + ks * 32 + half_ * 16;
                    ldsm_x4(bh[g * 2][0], bh[g * 2][1], bh[g * 2 + 1][0], bh[g * 2 + 1][1], ad);
                }
#pragma unroll
                for (int mf = 0; mf < 2; mf++)
#pragma unroll
                    for (int nf = 0; nf < 4; nf++)
                        mma_f16(acc[mf][hg * 4 + nf], ah[mf][0], ah[mf][1], ah[mf][2],
                                ah[mf][3], bh[nf][0], bh[nf][1]);
            }
        }
        if (c < DMODEL / GKC - 1) CPA_WAIT0();
        __syncthreads();
    }

    const int q4 = lane & 3, r4 = lane >> 2;
#pragma unroll
    for (int mf = 0; mf < 2; mf++)
#pragma unroll
        for (int nf = 0; nf < 8; nf++) {
            int col = bn + wn * 64 + nf * 8 + q4 * 2;
            float2 bb = *(const float2*)(bias + col);
#pragma unroll
            for (int hh = 0; hh < 2; hh++) {
                int row = bm + wm * 32 + mf * 16 + r4 + hh * 8;
                float v0 = acc[mf][nf][2 * hh + 0] + bb.x;
                float v1 = acc[mf][nf][2 * hh + 1] + bb.y;
                if (!QKV) {
                    *(float2*)(Cout + (size_t)row * DMODEL + col) = make_float2(v0, v1);
                } else {
                    if (z == 0) { v0 *= SCALE_LOG2E; v1 *= SCALE_LOG2E; }
                    int b = row >> 10, s = row & 1023, hd = col >> 6, d = col & 63;
                    size_t o = ((size_t)((b * NHEAD + hd) * SLEN + s)) * DKV + d;
                    uint32_t hp = pack2f(__float2half_rn(v0), __float2half_rn(v1));
                    __half* dst = (z == 0) ? g_qh : (z == 1) ? g_kh : g_vh;
                    *(uint32_t*)(dst + o) = hp;
                }
            }
        }
}

// ---------------------------------------------------------------------------
// Flash attention, fp16 mma.sync, fixed-max softmax (scale pre-folded into Q).
// Block: 64 q-rows x one (b,h). 4 warps / 128 threads.
// K and V are separate cp.async groups: QK waits only K, PV waits only V.
// ---------------------------------------------------------------------------
#define AROWB 144
#define AT_BYTES (64 * AROWB)            // 9216
#define ABUF (2 * AT_BYTES)              // Kh,Vh = 18432 per stage
#define ATTN_SMEM (2 * ABUF + AT_BYTES)  // + Q staging = 46080

__global__ __launch_bounds__(128) void attn_kernel()
{
    extern __shared__ char smem[];
    const uint32_t sb = smem_u32(smem);
    const int tid = threadIdx.x, lane = tid & 31, w = tid >> 5;
    const int q4 = lane & 3, r4 = lane >> 2;
    const int qt = blockIdx.x, bh = blockIdx.y;
    const int b = bh >> 3, h = bh & 7;

    const __half* Qh = g_qh + (size_t)bh * SLEN * DKV + (size_t)qt * 64 * DKV;
    const __half* Kh = g_kh + (size_t)bh * SLEN * DKV;
    const __half* Vh = g_vh + (size_t)bh * SLEN * DKV;

    auto load_K = [&](int kt, int st) {
        uint32_t dst = sb + st * ABUF;
        const __half* src = Kh + (size_t)kt * 64 * DKV;
#pragma unroll
        for (int it = 0; it < 4; it++) {
            int idx = tid + it * 128;
            int r = idx >> 3, cc = idx & 7;
            cpa16(dst + r * AROWB + cc * 16, src + r * DKV + cc * 8);
        }
        CPA_COMMIT();
    };
    auto load_V = [&](int kt, int st) {
        uint32_t dst = sb + st * ABUF + AT_BYTES;
        const __half* src = Vh + (size_t)kt * 64 * DKV;
#pragma unroll
        for (int it = 0; it < 4; it++) {
            int idx = tid + it * 128;
            int r = idx >> 3, cc = idx & 7;
            cpa16(dst + r * AROWB + cc * 16, src + r * DKV + cc * 8);
        }
        CPA_COMMIT();
    };

    // ---- stage Q + tile 0, then extract Q fragments ----
    {
        uint32_t qb = sb + 2 * ABUF;
#pragma unroll
        for (int it = 0; it < 4; it++) {
            int idx = tid + it * 128;
            int r = idx >> 3, cc = idx & 7;
            cpa16(qb + r * AROWB + cc * 16, Qh + r * DKV + cc * 8);
        }
        CPA_COMMIT();
    }
    load_K(0, 0);
    load_V(0, 0);
    CPA_WAIT0();
    __syncthreads();

    uint32_t qfh[4][4];
    {
        uint32_t qb = sb + 2 * ABUF;
        uint32_t row = w * 16 + (lane & 15);
#pragma unroll
        for (int ks = 0; ks < 4; ks++) {
            uint32_t col = ks * 32 + ((lane >> 4) << 4);
            ldsm_x4(qfh[ks][0], qfh[ks][1], qfh[ks][2], qfh[ks][3],
                    qb + row * AROWB + col);
        }
    }

    float o[8][4];
#pragma unroll
    for (int j = 0; j < 8; j++)
#pragma unroll
        for (int k = 0; k < 4; k++) o[j][k] = 0.f;
    float l0 = 0.f, l1 = 0.f;

    const uint32_t* mrow0 = g_mbits + ((size_t)b * SLEN + qt * 64 + w * 16 + r4) * 32;
    const uint32_t* mrow1 = mrow0 + 8 * 32;

    const int m4 = lane >> 3, half_ = m4 & 1, sub = m4 >> 1;

    for (int kt = 0; kt < 16; ++kt) {
        int st = kt & 1;
        if (kt < 15) {                 // two groups: K first, then V
            load_K(kt + 1, st ^ 1);
            load_V(kt + 1, st ^ 1);
        }
        uint32_t base = sb + st * ABUF;

        // ---- S = Q @ K^T (K(kt) resident from previous tile's wait) ----
        float s[8][4];
#pragma unroll
        for (int j = 0; j < 8; j++)
#pragma unroll
            for (int k = 0; k < 4; k++) s[j][k] = 0.f;

#pragma unroll
        for (int ks = 0; ks < 4; ks++) {
            uint32_t kh[8][2];
#pragma unroll
            for (int g = 0; g < 4; g++) {
                uint32_t row = (g * 2 + sub) * 8 + (lane & 7);
                uint32_t ad = base + row * AROWB + ks * 32 + half_ * 16;
                ldsm_x4(kh[g * 2][0], kh[g * 2][1], kh[g * 2 + 1][0], kh[g * 2 + 1][1], ad);
            }
#pragma unroll
            for (int nf = 0; nf < 8; nf++)
                mma_f16(s[nf], qfh[ks][0], qfh[ks][1], qfh[ks][2], qfh[ks][3],
                        kh[nf][0], kh[nf][1]);
        }

        // ---- mask + exp2 (scale folded into Q) ----
        uint32_t w0a = mrow0[kt * 2], w0b = mrow0[kt * 2 + 1];
        uint32_t w1a = mrow1[kt * 2], w1b = mrow1[kt * 2 + 1];
        uint32_t pH01[8], pH23[8];
#pragma unroll
        for (int nf = 0; nf < 8; nf++) {
            int c = nf * 8 + q4 * 2;
            uint32_t wr0 = (c < 32) ? w0a : w0b;
            uint32_t wr1 = (c < 32) ? w1a : w1b;
            int sh = c & 31;
            float p0 = ((wr0 >> sh) & 1) ? 0.f : ex2f(s[nf][0]);
            float p1 = ((wr0 >> (sh + 1)) & 1) ? 0.f : ex2f(s[nf][1]);
            float p2 = ((wr1 >> sh) & 1) ? 0.f : ex2f(s[nf][2]);
            float p3 = ((wr1 >> (sh + 1)) & 1) ? 0.f : ex2f(s[nf][3]);
            l0 += p0 + p1;
            l1 += p2 + p3;
            pH01[nf] = pack2f(__float2half_rn(p0), __float2half_rn(p1));
            pH23[nf] = pack2f(__float2half_rn(p2), __float2half_rn(p3));
        }

        // ---- wait V(kt) only (K(kt+1)/V(kt+1) may still be in flight) ----
        if (kt < 15) { CPA_WAIT2(); } else { CPA_WAIT0(); }
        __syncthreads();

        // ---- O += P @ V ----
#pragma unroll
        for (int ks = 0; ks < 4; ks++) {
            uint32_t a0 = pH01[2 * ks], a1 = pH23[2 * ks];
            uint32_t a2 = pH01[2 * ks + 1], a3 = pH23[2 * ks + 1];
            uint32_t vaddr = (ks * 16 + (lane & 15)) * AROWB + ((lane >> 4) << 4);
            uint32_t vh[16];
#pragma unroll
            for (int nf2 = 0; nf2 < 4; nf2++) {
                ldsm_x4t(vh[nf2 * 4 + 0], vh[nf2 * 4 + 1], vh[nf2 * 4 + 2], vh[nf2 * 4 + 3],
                         base + 1 * AT_BYTES + vaddr + nf2 * 32);
            }
#pragma unroll
            for (int j = 0; j < 8; j++)
                mma_f16(o[j], a0, a1, a2, a3, vh[2 * j], vh[2 * j + 1]);
        }

        if (kt < 15) {
            CPA_WAIT1();       // K(kt+1) done (V(kt+1) may still be loading)
            __syncthreads();
        }
    }

    // ---- one-time row-sum reduction ----
    l0 += __shfl_xor_sync(0xffffffffu, l0, 1);
    l0 += __shfl_xor_sync(0xffffffffu, l0, 2);
    l1 += __shfl_xor_sync(0xffffffffu, l1, 1);
    l1 += __shfl_xor_sync(0xffffffffu, l1, 2);

    // ---- epilogue: ctx = O / l -> fp16 into g_ah ----
    float il0 = (l0 > 0.f) ? (1.f / l0) : 0.f;
    float il1 = (l1 > 0.f) ? (1.f / l1) : 0.f;
    int row0 = qt * 64 + w * 16 + r4;
#pragma unroll
    for (int nf = 0; nf < 8; nf++) {
        int col = h * 64 + nf * 8 + q4 * 2;
        uint32_t hp = pack2f(__float2half_rn(o[nf][0] * il0), __float2half_rn(o[nf][1] * il0));
        *(uint32_t*)(g_ah + (size_t)(b * SLEN + row0) * DMODEL + col) = hp;
        hp = pack2f(__float2half_rn(o[nf][2] * il1), __float2half_rn(o[nf][3] * il1));
        *(uint32_t*)(g_ah + (size_t)(b * SLEN + row0 + 8) * DMODEL + col) = hp;
    }
}

// ---------------------------------------------------------------------------
extern "C" void kernel_launch(void* const* d_in, const int* in_sizes, int n_in,
                              void* d_out, int out_size)
{
    const float* inputs = (const float*)d_in[0];
    const float* mask   = (const float*)d_in[1];
    const float* wq = (const float*)d_in[2];
    const float* bq = (const float*)d_in[3];
    const float* wk = (const float*)d_in[4];
    const float* bk = (const float*)d_in[5];
    const float* wv = (const float*)d_in[6];
    const float* bv = (const float*)d_in[7];
    const float* wo = (const float*)d_in[8];
    const float* bo = (const float*)d_in[9];
    float* out = (float*)d_out;

    __half *ah, *wh;
    cudaGetSymbolAddress((void**)&ah, g_ah);
    cudaGetSymbolAddress((void**)&wh, g_wh);

    setup_kernel<<<NB_IN + 4 * NB_W + NB_MASK, 256>>>(inputs, wq, wk, wv, wo, mask);

    cudaFuncSetAttribute(mm_kernel<true>, cudaFuncAttributeMaxDynamicSharedMemorySize, GEMM_SMEM);
    cudaFuncSetAttribute(mm_kernel<false>, cudaFuncAttributeMaxDynamicSharedMemorySize, GEMM_SMEM);
    cudaFuncSetAttribute(attn_kernel, cudaFuncAttributeMaxDynamicSharedMemorySize, ATTN_SMEM);

    dim3 gqkv(DMODEL / 128, MROWS / 128, 3);   // (4, 64, 3)
    mm_kernel<true><<<gqkv, 256, GEMM_SMEM>>>(ah, wh, bq, bk, bv, nullptr);

    dim3 ga(SLEN / 64, BATCH * NHEAD);         // (16, 64)
    attn_kernel<<<ga, 128, ATTN_SMEM>>>();     // writes ctx fp16 into g_ah

    dim3 go(DMODEL / 128, MROWS / 128);        // (4, 64)
    mm_kernel<false><<<go, 256, GEMM_SMEM>>>(ah, wh + 3 * WSZ,
                                             bo, nullptr, nullptr, out);
}